// round 4
// baseline (speedup 1.0000x reference)
#include <cuda_runtime.h>
#include <cuda_bf16.h>

#define F_IN  512
#define HID   16
#define C_OUT 40
#define MAXN  100000
#define MAXE  3200000

typedef unsigned long long ull;

// ---------------- scratch (static device globals, no allocs) ----------------
__device__ __align__(128) int   g_deg [MAXN];
__device__ __align__(128) float g_dinv[MAXN];
__device__ __align__(128) float g_B1  [MAXN * HID];   // h~, later a~ (agg gather input)
__device__ __align__(128) float g_B2  [MAXN * HID];   // agg accumulators

// ---------------- helpers ----------------
__device__ __forceinline__ void red4(float* p, float a, float b, float c, float d) {
    asm volatile("red.global.add.v4.f32 [%0], {%1,%2,%3,%4};"
                 :: "l"(p), "f"(a), "f"(b), "f"(c), "f"(d) : "memory");
}
__device__ __forceinline__ ull pkdup(float v) {
    ull r;
    asm("mov.b64 %0, {%1, %1};" : "=l"(r) : "f"(v));
    return r;
}
__device__ __forceinline__ float2 upk2(ull v) {
    float2 f;
    asm("mov.b64 {%0, %1}, %2;" : "=f"(f.x), "=f"(f.y) : "l"(v));
    return f;
}
__device__ __forceinline__ void fma2(ull& d, ull a, ull b) {
    asm("fma.rn.f32x2 %0, %1, %2, %0;" : "+l"(d) : "l"(a), "l"(b));
}

// ---------------- small kernels ----------------
__global__ void k_zero(int* a, int N) {
    int i = blockIdx.x * blockDim.x + threadIdx.x;
    if (i < N) a[i] = 0;
}
__global__ void k_hist(const int* __restrict__ dst, int* deg, int E) {
    int i = blockIdx.x * blockDim.x + threadIdx.x;
    if (i < E) atomicAdd(&deg[dst[i]], 1);
}
__global__ void k_dinv(const int* __restrict__ deg, float* dinv, int N) {
    int i = blockIdx.x * blockDim.x + threadIdx.x;
    if (i < N) dinv[i] = rsqrtf((float)(deg[i] + 1));
}

// ---------------- GEMM1: h~ = dinv * (x @ W1), dual store ----------------
// 128 threads, 128 rows/block (1 row/thread), full K. 782 blocks x 4 warps.
#define G1_S 132   // padded k-row stride (floats) for the x tile
__global__ __launch_bounds__(128) void k_gemm1(const float* __restrict__ x,
                                               const float* __restrict__ W1,
                                               const float* __restrict__ dinv,
                                               float* __restrict__ h0,
                                               float* __restrict__ h1, int N) {
    __shared__ float sx[16 * G1_S];   // [kk][row]
    __shared__ ull   wt[16 * 8];      // [kk][colpair] raw W1 copy (16 k x 16 cols)
    const int t    = threadIdx.x;
    const int base = blockIdx.x * 128;
    const int rg   = base + t;
    const bool live = (rg < N);

    ull acc[8];
#pragma unroll
    for (int j = 0; j < 8; j++) acc[j] = 0ull;

    for (int kt = 0; kt < 32; kt++) {
        const int kg = kt * 16;
        __syncthreads();
        // W tile: 16 k-rows x 16 cols = 128 ull, coalesced
        wt[t] = ((const ull*)(W1 + (size_t)kg * 16))[t];
        // x tile: 128 rows x 16 k = 512 float4, 4 per thread
#pragma unroll
        for (int i = 0; i < 4; i++) {
            int c = t + 128 * i;
            int r = c >> 2, q = c & 3;
            float4 v = make_float4(0.f, 0.f, 0.f, 0.f);
            if (base + r < N)
                v = *(const float4*)&x[(size_t)(base + r) * F_IN + kg + q * 4];
            sx[(4 * q + 0) * G1_S + r] = v.x;
            sx[(4 * q + 1) * G1_S + r] = v.y;
            sx[(4 * q + 2) * G1_S + r] = v.z;
            sx[(4 * q + 3) * G1_S + r] = v.w;
        }
        __syncthreads();
#pragma unroll
        for (int kk = 0; kk < 16; kk++) {
            ull xa = pkdup(sx[kk * G1_S + t]);
            const ulonglong2* w2 = (const ulonglong2*)&wt[kk * 8];
#pragma unroll
            for (int p = 0; p < 4; p++) {
                ulonglong2 wv = w2[p];
                fma2(acc[2 * p + 0], xa, wv.x);
                fma2(acc[2 * p + 1], xa, wv.y);
            }
        }
    }
    if (live) {
        float dv = dinv[rg];
#pragma unroll
        for (int j4 = 0; j4 < 4; j4++) {
            float2 f0 = upk2(acc[2 * j4 + 0]);
            float2 f1 = upk2(acc[2 * j4 + 1]);
            float4 v = make_float4(f0.x * dv, f0.y * dv, f1.x * dv, f1.y * dv);
            *(float4*)&h0[(size_t)rg * HID + 4 * j4] = v;
            *(float4*)&h1[(size_t)rg * HID + 4 * j4] = v;
        }
    }
}

// ---------------- edge aggregation: out[dst] += in[src], 4 thr/edge ----------
__global__ void k_agg(const int* __restrict__ src, const int* __restrict__ dst,
                      const float4* __restrict__ in4, float* out, int E) {
    int tid = blockIdx.x * blockDim.x + threadIdx.x;
    int e = tid >> 2;
    int c = tid & 3;
    if (e < E) {
        int s = src[e];
        int d = dst[e];
        float4 v = __ldg(&in4[(size_t)s * 4 + c]);
        red4(&out[((size_t)d * 4 + c) * 4], v.x, v.y, v.z, v.w);
    }
}

// ---------------- a~ = dinv * relu(dinv * y1 + b1), dual store --------------
__global__ void k_relubias(const float4* __restrict__ in4, const float* __restrict__ dinv,
                           const float* __restrict__ b1,
                           float4* __restrict__ o0, float4* __restrict__ o1, int N) {
    int i = blockIdx.x * blockDim.x + threadIdx.x;
    if (i < N * (HID / 4)) {
        float dv = dinv[i >> 2];
        int jb = (i & 3) * 4;
        float4 v = in4[i];
        v.x = fmaxf(fmaf(v.x, dv, b1[jb + 0]), 0.f) * dv;
        v.y = fmaxf(fmaf(v.y, dv, b1[jb + 1]), 0.f) * dv;
        v.z = fmaxf(fmaf(v.z, dv, b1[jb + 2]), 0.f) * dv;
        v.w = fmaxf(fmaf(v.w, dv, b1[jb + 3]), 0.f) * dv;
        o0[i] = v;
        o1[i] = v;
    }
}

// ---------------- GEMM2 + b2 ----------------
__global__ __launch_bounds__(128) void k_gemm2(const float* __restrict__ y2,
                                               const float* __restrict__ dinv,
                                               const float* __restrict__ W2,
                                               const float* __restrict__ b2,
                                               float* __restrict__ out, int N) {
    __shared__ float w2s[HID * C_OUT];
    __shared__ float b2s[C_OUT];
    int t = threadIdx.x;
    for (int i = t; i < HID * C_OUT; i += 128) w2s[i] = W2[i];
    if (t < C_OUT) b2s[t] = b2[t];
    __syncthreads();
    int i = blockIdx.x * 128 + t;
    if (i >= N) return;
    float dv = dinv[i];
    float a[HID];
#pragma unroll
    for (int k4 = 0; k4 < 4; k4++) {
        float4 v = *(const float4*)&y2[(size_t)i * HID + 4 * k4];
        a[4 * k4 + 0] = v.x * dv; a[4 * k4 + 1] = v.y * dv;
        a[4 * k4 + 2] = v.z * dv; a[4 * k4 + 3] = v.w * dv;
    }
    float o[C_OUT];
#pragma unroll
    for (int j = 0; j < C_OUT; j++) o[j] = b2s[j];
#pragma unroll
    for (int k = 0; k < HID; k++) {
        float av = a[k];
#pragma unroll
        for (int j = 0; j < C_OUT; j++) o[j] += av * w2s[k * C_OUT + j];
    }
#pragma unroll
    for (int jg = 0; jg < C_OUT / 4; jg++) {
        float4 v = make_float4(o[4 * jg + 0], o[4 * jg + 1], o[4 * jg + 2], o[4 * jg + 3]);
        *(float4*)&out[(size_t)i * C_OUT + 4 * jg] = v;
    }
}

// ---------------- launcher ----------------
extern "C" void kernel_launch(void* const* d_in, const int* in_sizes, int n_in,
                              void* d_out, int out_size) {
    const float* x  = (const float*)d_in[0];
    const int*   ei = (const int*)d_in[1];
    const float* W1 = (const float*)d_in[2];
    const float* b1 = (const float*)d_in[3];
    const float* W2 = (const float*)d_in[4];
    const float* b2 = (const float*)d_in[5];
    float* out = (float*)d_out;

    const int N = in_sizes[0] / F_IN;
    const int E = in_sizes[1] / 2;
    const int* src = ei;
    const int* dst = ei + E;

    void *p;
    cudaGetSymbolAddress(&p, g_deg);  int*   deg  = (int*)p;
    cudaGetSymbolAddress(&p, g_dinv); float* dinv = (float*)p;
    cudaGetSymbolAddress(&p, g_B1);   float* B1   = (float*)p;
    cudaGetSymbolAddress(&p, g_B2);   float* B2   = (float*)p;

    const int TB = 256;
    const int nv4 = N * (HID / 4);

    // launch 0-2: degree + dinv
    k_zero<<<(N + TB - 1) / TB, TB>>>(deg, N);
    k_hist<<<(E + TB - 1) / TB, TB>>>(dst, deg, E);
    k_dinv<<<(N + TB - 1) / TB, TB>>>(deg, dinv, N);
    // launch 3 (profiled): h~ = dinv * (x @ W1) -> B1 and B2 (self-loop init)
    k_gemm1<<<(N + 127) / 128, 128>>>(x, W1, dinv, B1, B2, N);
    // launch 4: B2 += A * B1
    {
        int threads = E * 4;
        k_agg<<<(threads + TB - 1) / TB, TB>>>(src, dst, (const float4*)B1, B2, E);
    }
    // launch 5: a~ -> B1 and B2
    k_relubias<<<(nv4 + TB - 1) / TB, TB>>>((const float4*)B2, dinv, b1,
                                            (float4*)B1, (float4*)B2, N);
    // launch 6: B2 += A * B1
    {
        int threads = E * 4;
        k_agg<<<(threads + TB - 1) / TB, TB>>>(src, dst, (const float4*)B1, B2, E);
    }
    // launch 7: out = (dinv * B2) @ W2 + b2
    k_gemm2<<<(N + 127) / 128, 128>>>(B2, dinv, W2, b2, out, N);
}

// round 5
// speedup vs baseline: 1.1083x; 1.1083x over previous
#include <cuda_runtime.h>
#include <cuda_bf16.h>

#define F_IN  512
#define HID   16
#define C_OUT 40
#define MAXN  100000
#define MAXE  3200000

typedef unsigned long long ull;

// ---------------- scratch (static device globals, no allocs) ----------------
__device__ __align__(128) int   g_deg [MAXN];
__device__ __align__(128) float g_dinv[MAXN];
__device__ __align__(128) float g_B1  [MAXN * HID];   // h~, later a~ (agg gather input)
__device__ __align__(128) float g_B2  [MAXN * HID];   // agg accumulators

// ---------------- helpers ----------------
__device__ __forceinline__ void red4(float* p, float a, float b, float c, float d) {
    asm volatile("red.global.add.v4.f32 [%0], {%1,%2,%3,%4};"
                 :: "l"(p), "f"(a), "f"(b), "f"(c), "f"(d) : "memory");
}
__device__ __forceinline__ ull pkdup(float v) {
    ull r;
    asm("mov.b64 %0, {%1, %1};" : "=l"(r) : "f"(v));
    return r;
}
__device__ __forceinline__ float2 upk2(ull v) {
    float2 f;
    asm("mov.b64 {%0, %1}, %2;" : "=f"(f.x), "=f"(f.y) : "l"(v));
    return f;
}
__device__ __forceinline__ void fma2(ull& d, ull a, ull b) {
    asm("fma.rn.f32x2 %0, %1, %2, %0;" : "+l"(d) : "l"(a), "l"(b));
}

// ---------------- fused zero: deg + B1 + B2 ----------------
__global__ void k_zero_all(int* deg, float4* b1, float4* b2, int N, int nv4) {
    int i = blockIdx.x * blockDim.x + threadIdx.x;
    if (i < N) deg[i] = 0;
    if (i < nv4) {
        b1[i] = make_float4(0.f, 0.f, 0.f, 0.f);
        b2[i] = make_float4(0.f, 0.f, 0.f, 0.f);
    }
}
__global__ void k_hist(const int* __restrict__ dst, int* deg, int E) {
    int i = blockIdx.x * blockDim.x + threadIdx.x;
    if (i < E) atomicAdd(&deg[dst[i]], 1);
}
__global__ void k_dinv(const int* __restrict__ deg, float* dinv, int N) {
    int i = blockIdx.x * blockDim.x + threadIdx.x;
    if (i < N) dinv[i] = rsqrtf((float)(deg[i] + 1));
}

// ---------------- GEMM1 v3: h~ += dinv * (x @ W1) partials, K-split 2 -------
// 128 threads, 512 rows/block, 4 rows/thread (t, t+128, t+256, t+384), 16 cols.
// x tile row-major float4 [512][G1_RS], vector STS/LDS; w broadcast LDS.128.
#define G1_RS 5   // row stride in float4 units (4 data + 1 pad)
__global__ __launch_bounds__(128) void k_gemm1(const float* __restrict__ x,
                                               const float* __restrict__ W1,
                                               const float* __restrict__ dinv,
                                               float* __restrict__ h0,
                                               float* __restrict__ h1, int N) {
    __shared__ float4 sx[512 * G1_RS];   // 40KB
    __shared__ ull    wt[128];           // 16 kk x 16 cols = 128 ull (1KB)
    const int t    = threadIdx.x;
    const int base = blockIdx.x * 512;
    const int k0   = blockIdx.y * 256;

    ull acc[4][8];
#pragma unroll
    for (int m = 0; m < 4; m++)
#pragma unroll
        for (int j = 0; j < 8; j++) acc[m][j] = 0ull;

    for (int kt = 0; kt < 16; kt++) {
        const int kg = k0 + kt * 16;
        __syncthreads();
        // w tile: 16 k-rows x 16 cols, coalesced (1 ull/thread)
        wt[t] = ((const ull*)(W1 + (size_t)kg * 16))[t];
        // x tile: 512 rows x 4 float4 = 2048 f4, 16 per thread
#pragma unroll
        for (int j = 0; j < 16; j++) {
            int idx = t + 128 * j;
            int r = idx >> 2, q = idx & 3;
            float4 v = make_float4(0.f, 0.f, 0.f, 0.f);
            if (base + r < N)
                v = *(const float4*)&x[(size_t)(base + r) * F_IN + kg + q * 4];
            sx[r * G1_RS + q] = v;
        }
        __syncthreads();
#pragma unroll
        for (int g = 0; g < 4; g++) {
            float4 xr[4];
#pragma unroll
            for (int m = 0; m < 4; m++)
                xr[m] = sx[(t + 128 * m) * G1_RS + g];
#pragma unroll
            for (int e = 0; e < 4; e++) {
                const ulonglong2* w2 = (const ulonglong2*)&wt[(4 * g + e) * 8];
                ulonglong2 wa = w2[0], wb = w2[1], wc = w2[2], wd = w2[3];
#pragma unroll
                for (int m = 0; m < 4; m++) {
                    float s = (e == 0) ? xr[m].x : (e == 1) ? xr[m].y
                            : (e == 2) ? xr[m].z : xr[m].w;
                    ull xs = pkdup(s);
                    fma2(acc[m][0], xs, wa.x); fma2(acc[m][1], xs, wa.y);
                    fma2(acc[m][2], xs, wb.x); fma2(acc[m][3], xs, wb.y);
                    fma2(acc[m][4], xs, wc.x); fma2(acc[m][5], xs, wc.y);
                    fma2(acc[m][6], xs, wd.x); fma2(acc[m][7], xs, wd.y);
                }
            }
        }
    }
    // epilogue: scale partial by dinv (linear in the K-sum) and red into both bufs
#pragma unroll
    for (int m = 0; m < 4; m++) {
        int rg = base + t + 128 * m;
        if (rg < N) {
            float dv = dinv[rg];
#pragma unroll
            for (int j4 = 0; j4 < 4; j4++) {
                float2 f0 = upk2(acc[m][2 * j4 + 0]);
                float2 f1 = upk2(acc[m][2 * j4 + 1]);
                float a = f0.x * dv, b = f0.y * dv, c = f1.x * dv, d = f1.y * dv;
                red4(&h0[(size_t)rg * HID + 4 * j4], a, b, c, d);
                red4(&h1[(size_t)rg * HID + 4 * j4], a, b, c, d);
            }
        }
    }
}

// ---------------- edge aggregation: out[dst] += in[src], 4 thr/edge ----------
__global__ void k_agg(const int* __restrict__ src, const int* __restrict__ dst,
                      const float4* __restrict__ in4, float* out, int E) {
    int tid = blockIdx.x * blockDim.x + threadIdx.x;
    int e = tid >> 2;
    int c = tid & 3;
    if (e < E) {
        int s = src[e];
        int d = dst[e];
        float4 v = __ldg(&in4[(size_t)s * 4 + c]);
        red4(&out[((size_t)d * 4 + c) * 4], v.x, v.y, v.z, v.w);
    }
}

// ---------------- a~ = dinv * relu(dinv * y1 + b1), dual store --------------
__global__ void k_relubias(const float4* __restrict__ in4, const float* __restrict__ dinv,
                           const float* __restrict__ b1,
                           float4* __restrict__ o0, float4* __restrict__ o1, int N) {
    int i = blockIdx.x * blockDim.x + threadIdx.x;
    if (i < N * (HID / 4)) {
        float dv = dinv[i >> 2];
        int jb = (i & 3) * 4;
        float4 v = in4[i];
        v.x = fmaxf(fmaf(v.x, dv, b1[jb + 0]), 0.f) * dv;
        v.y = fmaxf(fmaf(v.y, dv, b1[jb + 1]), 0.f) * dv;
        v.z = fmaxf(fmaf(v.z, dv, b1[jb + 2]), 0.f) * dv;
        v.w = fmaxf(fmaf(v.w, dv, b1[jb + 3]), 0.f) * dv;
        o0[i] = v;
        o1[i] = v;
    }
}

// ---------------- GEMM2 + b2 ----------------
__global__ __launch_bounds__(128) void k_gemm2(const float* __restrict__ y2,
                                               const float* __restrict__ dinv,
                                               const float* __restrict__ W2,
                                               const float* __restrict__ b2,
                                               float* __restrict__ out, int N) {
    __shared__ float w2s[HID * C_OUT];
    __shared__ float b2s[C_OUT];
    int t = threadIdx.x;
    for (int i = t; i < HID * C_OUT; i += 128) w2s[i] = W2[i];
    if (t < C_OUT) b2s[t] = b2[t];
    __syncthreads();
    int i = blockIdx.x * 128 + t;
    if (i >= N) return;
    float dv = dinv[i];
    float a[HID];
#pragma unroll
    for (int k4 = 0; k4 < 4; k4++) {
        float4 v = *(const float4*)&y2[(size_t)i * HID + 4 * k4];
        a[4 * k4 + 0] = v.x * dv; a[4 * k4 + 1] = v.y * dv;
        a[4 * k4 + 2] = v.z * dv; a[4 * k4 + 3] = v.w * dv;
    }
    float o[C_OUT];
#pragma unroll
    for (int j = 0; j < C_OUT; j++) o[j] = b2s[j];
#pragma unroll
    for (int k = 0; k < HID; k++) {
        float av = a[k];
#pragma unroll
        for (int j = 0; j < C_OUT; j++) o[j] += av * w2s[k * C_OUT + j];
    }
#pragma unroll
    for (int jg = 0; jg < C_OUT / 4; jg++) {
        float4 v = make_float4(o[4 * jg + 0], o[4 * jg + 1], o[4 * jg + 2], o[4 * jg + 3]);
        *(float4*)&out[(size_t)i * C_OUT + 4 * jg] = v;
    }
}

// ---------------- launcher ----------------
extern "C" void kernel_launch(void* const* d_in, const int* in_sizes, int n_in,
                              void* d_out, int out_size) {
    const float* x  = (const float*)d_in[0];
    const int*   ei = (const int*)d_in[1];
    const float* W1 = (const float*)d_in[2];
    const float* b1 = (const float*)d_in[3];
    const float* W2 = (const float*)d_in[4];
    const float* b2 = (const float*)d_in[5];
    float* out = (float*)d_out;

    const int N = in_sizes[0] / F_IN;
    const int E = in_sizes[1] / 2;
    const int* src = ei;
    const int* dst = ei + E;

    void *p;
    cudaGetSymbolAddress(&p, g_deg);  int*   deg  = (int*)p;
    cudaGetSymbolAddress(&p, g_dinv); float* dinv = (float*)p;
    cudaGetSymbolAddress(&p, g_B1);   float* B1   = (float*)p;
    cudaGetSymbolAddress(&p, g_B2);   float* B2   = (float*)p;

    const int TB = 256;
    const int nv4 = N * (HID / 4);

    // launch 0-2: zero + degree + dinv
    k_zero_all<<<(nv4 + TB - 1) / TB, TB>>>(deg, (float4*)B1, (float4*)B2, N, nv4);
    k_hist<<<(E + TB - 1) / TB, TB>>>(dst, deg, E);
    k_dinv<<<(N + TB - 1) / TB, TB>>>(deg, dinv, N);
    // launch 3 (profiled): h~ = dinv * (x @ W1) -> red into B1 and B2
    {
        dim3 grid((N + 511) / 512, 2);
        k_gemm1<<<grid, 128>>>(x, W1, dinv, B1, B2, N);
    }
    // launch 4: B2 += A * B1
    {
        int threads = E * 4;
        k_agg<<<(threads + TB - 1) / TB, TB>>>(src, dst, (const float4*)B1, B2, E);
    }
    // launch 5: a~ -> B1 and B2
    k_relubias<<<(nv4 + TB - 1) / TB, TB>>>((const float4*)B2, dinv, b1,
                                            (float4*)B1, (float4*)B2, N);
    // launch 6: B2 += A * B1
    {
        int threads = E * 4;
        k_agg<<<(threads + TB - 1) / TB, TB>>>(src, dst, (const float4*)B1, B2, E);
    }
    // launch 7: out = (dinv * B2) @ W2 + b2
    k_gemm2<<<(N + 127) / 128, 128>>>(B2, dinv, W2, b2, out, N);
}